// round 4
// baseline (speedup 1.0000x reference)
#include <cuda_runtime.h>
#include <cstdint>
#include <math.h>

#define NB_ 64
#define NS_ 512
#define NHID_ 256
#define NTAGS_ 9
#define LOGITS_N (NB_ * NS_ * NTAGS_)   // 294912
#define LENS_OFF LOGITS_N               // 294912
#define LL_OFF   (LOGITS_N + NB_)       // 294976

// Scratch (device globals: no allocation allowed)
__device__ float g_xzf[NB_ * NS_ * 1024];   // x @ W_f + b_f
__device__ float g_xzb[NB_ * NS_ * 1024];   // x @ W_b + b_b
__device__ float g_hf[NB_ * NS_ * NHID_];
__device__ float g_hb[NB_ * NS_ * NHID_];

// ---------------- packed f32x2 helpers (sm_103a FFMA2 path) ----------------
__device__ __forceinline__ unsigned long long pk2(float lo, float hi) {
    unsigned long long r;
    asm("mov.b64 %0, {%1, %2};" : "=l"(r) : "f"(lo), "f"(hi));
    return r;
}
__device__ __forceinline__ float2 unpk2(unsigned long long v) {
    float2 r;
    asm("mov.b64 {%0, %1}, %2;" : "=f"(r.x), "=f"(r.y) : "l"(v));
    return r;
}
__device__ __forceinline__ unsigned long long fma2_(unsigned long long a,
                                                    unsigned long long b,
                                                    unsigned long long c) {
    unsigned long long d;
    asm("fma.rn.f32x2 %0, %1, %2, %3;" : "=l"(d) : "l"(a), "l"(b), "l"(c));
    return d;
}
__device__ __forceinline__ unsigned long long add2_(unsigned long long a,
                                                    unsigned long long b) {
    unsigned long long d;
    asm("add.rn.f32x2 %0, %1, %2;" : "=l"(d) : "l"(a), "l"(b));
    return d;
}

__device__ __forceinline__ float fsig(float x) {
    return __fdividef(1.0f, 1.0f + __expf(-x));
}
__device__ __forceinline__ float ftanh_(float x) {
    x = fminf(fmaxf(x, -15.0f), 15.0f);
    float e = __expf(2.0f * x);
    return __fdividef(e - 1.0f, e + 1.0f);
}

// ---------------------------------------------------------------------------
// K1: fused embedding-gather + input GEMM.
// A tile stored DUPLICATED in smem ((a,a) u64 pairs) so the broadcast operand
// of FFMA2 needs no per-iteration packing; B read as native u64 column pairs.
// Grid: (512, 32): x = M tile (64 rows), y<16 -> fwd cols, y>=16 -> bwd cols.
// ---------------------------------------------------------------------------
__global__ void __launch_bounds__(256, 2)
k_ingemm(const int* __restrict__ text, const float* __restrict__ emb,
         const float* __restrict__ Wf, const float* __restrict__ bf,
         const float* __restrict__ Wb, const float* __restrict__ bb)
{
    extern __shared__ char sm1raw[];
    unsigned long long* As2 = (unsigned long long*)sm1raw;   // 64 x 130 u64 (dup, padded)
    float* Bs = (float*)(As2 + 64 * 130);                    // 128 x 64 f32
    int*   toks = (int*)(Bs + 128 * 64);                     // 64

    int bx = blockIdx.x, by = blockIdx.y, tid = threadIdx.x;
    const float* W; const float* bias; float* out; int ncol0;
    if (by < 16) { W = Wf; bias = bf; out = g_xzf; ncol0 = by * 64; }
    else         { W = Wb; bias = bb; out = g_xzb; ncol0 = (by - 16) * 64; }

    if (tid < 64) toks[tid] = text[bx * 64 + tid];
    __syncthreads();

    // A tile: gather + duplicate
    for (int i = tid; i < 2048; i += 256) {
        int m = i >> 5, k4 = i & 31;
        float4 v = __ldg((const float4*)(emb + (size_t)toks[m] * 128) + k4);
        ulonglong2 d0, d1;
        d0.x = pk2(v.x, v.x); d0.y = pk2(v.y, v.y);
        d1.x = pk2(v.z, v.z); d1.y = pk2(v.w, v.w);
        *(ulonglong2*)(As2 + m * 130 + k4 * 4)     = d0;
        *(ulonglong2*)(As2 + m * 130 + k4 * 4 + 2) = d1;
    }
    // B tile: 128 x 64
    for (int i = tid; i < 2048; i += 256) {
        int k = i >> 4, n4 = i & 15;
        float4 v = __ldg((const float4*)(W + (size_t)k * 1024 + ncol0) + n4);
        *(float4*)(Bs + k * 64 + n4 * 4) = v;
    }
    __syncthreads();

    int tx = tid & 15, ty = tid >> 4;
    const unsigned long long* Bu = (const unsigned long long*)Bs;
    unsigned long long a01[4], a23[4];
#pragma unroll
    for (int i = 0; i < 4; i++) { a01[i] = 0ULL; a23[i] = 0ULL; }

#pragma unroll 2
    for (int kb = 0; kb < 128; kb += 4) {
        ulonglong2 ar0[4], ar1[4];
#pragma unroll
        for (int i = 0; i < 4; i++) {
            ar0[i] = *(const ulonglong2*)(As2 + (ty * 4 + i) * 130 + kb);
            ar1[i] = *(const ulonglong2*)(As2 + (ty * 4 + i) * 130 + kb + 2);
        }
#pragma unroll
        for (int kq = 0; kq < 4; kq++) {
            ulonglong2 b2 = *(const ulonglong2*)(Bu + (size_t)(kb + kq) * 32 + tx * 2);
#pragma unroll
            for (int i = 0; i < 4; i++) {
                unsigned long long ad = (kq == 0) ? ar0[i].x : (kq == 1) ? ar0[i].y
                                      : (kq == 2) ? ar1[i].x : ar1[i].y;
                a01[i] = fma2_(ad, b2.x, a01[i]);
                a23[i] = fma2_(ad, b2.y, a23[i]);
            }
        }
    }

    float4 bvv = *(const float4*)(bias + ncol0 + tx * 4);
#pragma unroll
    for (int i = 0; i < 4; i++) {
        float2 p01 = unpk2(a01[i]), p23 = unpk2(a23[i]);
        float4 o;
        o.x = p01.x + bvv.x; o.y = p01.y + bvv.y;
        o.z = p23.x + bvv.z; o.w = p23.y + bvv.w;
        *(float4*)(out + (size_t)(bx * 64 + ty * 4 + i) * 1024 + ncol0 + tx * 4) = o;
    }
}

// ---------------------------------------------------------------------------
// K2: LSTM recurrence. 16 clusters x 8 CTAs (dir, batch-group of 8 rows).
// Per CTA: 32 hidden units (gate-interleaved cols c = unit*4+gate).
// U slice lives DUPLICATED in registers (packed once). h state stored
// TRANSPOSED [k][batch] in smem so batch-pairs load directly as u64 ->
// zero packing in the FFMA2 inner loop. 16 warps split K (16 each),
// partial z in smem (u64 batch-pairs), 128 consumer threads (bp,jj) do
// reduce + gates for 2 batches each + DSMEM v2 push of (h_b0,h_b1).
// ---------------------------------------------------------------------------
__global__ void __cluster_dims__(8, 1, 1) __launch_bounds__(512, 1)
k_lstm(const float* __restrict__ Uf, const float* __restrict__ Ub)
{
    extern __shared__ float sm2[];
    float* hbt = sm2;                                        // 2 x 256 x 8 f32 = 16KB
    unsigned long long* zpu = (unsigned long long*)(sm2 + 4096); // 64 x 132 u64 = 67.6KB

    int tid = threadIdx.x;
    unsigned rank;
    asm("mov.u32 %0, %%cluster_ctarank;" : "=r"(rank));
    int cl = blockIdx.x >> 3;
    int dir = cl & 1, bg = cl >> 1;
    const float* U    = dir ? Ub     : Uf;
    const float* xz   = dir ? g_xzb  : g_xzf;
    float*       hout = dir ? g_hb   : g_hf;

    int w = tid >> 5, l = tid & 31;
    int k0 = w * 16;

    // Preload U slice into registers, duplicated: ud[kk][g] = (u,u)
    // col c = l*4+g  maps to original col g*256 + rank*32 + l
    unsigned long long ud[16][4];
#pragma unroll
    for (int kk = 0; kk < 16; kk++) {
#pragma unroll
        for (int g = 0; g < 4; g++) {
            float v = __ldg(U + (size_t)(k0 + kk) * 1024 + g * 256 + rank * 32 + l);
            ud[kk][g] = pk2(v, v);
        }
    }
    for (int i = tid; i < 4096; i += 512) hbt[i] = 0.0f;

    bool cons = (tid < 128);
    int bp = tid >> 5;          // consumer batch-pair 0..3
    int jj = l;                 // consumer unit
    int b0 = bg * 8 + 2 * bp, b1 = b0 + 1;
    float cst0 = 0.f, cst1 = 0.f;
    float h0new = 0.f, h1new = 0.f;
    uint32_t ra[8];
    float x[8];
    if (cons) {
        uint32_t hb_addr = (uint32_t)__cvta_generic_to_shared(hbt);
        uint32_t loff = hb_addr + (uint32_t)(((rank * 32 + jj) * 8 + 2 * bp) * 4);
#pragma unroll
        for (int dc = 0; dc < 8; dc++)
            asm volatile("mapa.shared::cluster.u32 %0, %1, %2;" : "=r"(ra[dc]) : "r"(loff), "r"(dc));
        // prime xz for step 0
        int t0 = dir ? 511 : 0;
        const float* xp0 = xz + ((size_t)b0 * 512 + t0) * 1024 + rank * 32 + jj;
        const float* xp1 = xz + ((size_t)b1 * 512 + t0) * 1024 + rank * 32 + jj;
        x[0] = __ldg(xp0); x[1] = __ldg(xp0 + 256); x[2] = __ldg(xp0 + 512); x[3] = __ldg(xp0 + 768);
        x[4] = __ldg(xp1); x[5] = __ldg(xp1 + 256); x[6] = __ldg(xp1 + 512); x[7] = __ldg(xp1 + 768);
    }
    asm volatile("barrier.cluster.arrive.aligned;\n\tbarrier.cluster.wait.aligned;" ::: "memory");

    for (int n = 0; n < 512; n++) {
        int cur = n & 1, nxt = cur ^ 1;
        int t = dir ? (511 - n) : n;

        // GEMM: batch-pairs in f32x2 lanes, U duplicated in regs, h from smem as u64
        const ulonglong2* H2 = (const ulonglong2*)(hbt + cur * 2048);
        unsigned long long acc[4][4];
#pragma unroll
        for (int p = 0; p < 4; p++)
#pragma unroll
            for (int g = 0; g < 4; g++) acc[p][g] = 0ULL;

#pragma unroll
        for (int kk = 0; kk < 16; kk++) {
            int k = k0 + kk;
            ulonglong2 hA = H2[k * 2];       // (b0,b1),(b2,b3)
            ulonglong2 hB = H2[k * 2 + 1];   // (b4,b5),(b6,b7)
#pragma unroll
            for (int g = 0; g < 4; g++) {
                acc[0][g] = fma2_(hA.x, ud[kk][g], acc[0][g]);
                acc[1][g] = fma2_(hA.y, ud[kk][g], acc[1][g]);
                acc[2][g] = fma2_(hB.x, ud[kk][g], acc[2][g]);
                acc[3][g] = fma2_(hB.y, ud[kk][g], acc[3][g]);
            }
        }
#pragma unroll
        for (int p = 0; p < 4; p++) {
            ulonglong2 v0, v1;
            v0.x = acc[p][0]; v0.y = acc[p][1];
            v1.x = acc[p][2]; v1.y = acc[p][3];
            *(ulonglong2*)(zpu + (w * 4 + p) * 132 + 4 * l)     = v0;
            *(ulonglong2*)(zpu + (w * 4 + p) * 132 + 4 * l + 2) = v1;
        }
        __syncthreads();

        if (cons) {
            unsigned long long s0 = 0ULL, s1 = 0ULL, s2 = 0ULL, s3 = 0ULL;
#pragma unroll
            for (int w2 = 0; w2 < 16; w2++) {
                const ulonglong2* pz = (const ulonglong2*)(zpu + (w2 * 4 + bp) * 132 + 4 * jj);
                ulonglong2 a = pz[0], b = pz[1];
                s0 = add2_(s0, a.x); s1 = add2_(s1, a.y);
                s2 = add2_(s2, b.x); s3 = add2_(s3, b.y);
            }
            float2 zi = unpk2(s0), zf = unpk2(s1), zg = unpk2(s2), zo = unpk2(s3);
            float i0 = fsig(zi.x + x[0]), f0 = fsig(zf.x + x[1]);
            float g0 = ftanh_(zg.x + x[2]), o0 = fsig(zo.x + x[3]);
            float i1 = fsig(zi.y + x[4]), f1 = fsig(zf.y + x[5]);
            float g1 = ftanh_(zg.y + x[6]), o1 = fsig(zo.y + x[7]);
            cst0 = f0 * cst0 + i0 * g0;
            cst1 = f1 * cst1 + i1 * g1;
            h0new = o0 * ftanh_(cst0);
            h1new = o1 * ftanh_(cst1);

            uint32_t poff = (uint32_t)(nxt * 2048 * 4);
#pragma unroll
            for (int dc = 0; dc < 8; dc++)
                asm volatile("st.shared::cluster.v2.f32 [%0], {%1, %2};"
                             :: "r"(ra[dc] + poff), "f"(h0new), "f"(h1new));
        }
        asm volatile("barrier.cluster.arrive.aligned;" ::: "memory");

        // barrier shadow: global h stores + next-step xz prefetch
        if (cons) {
            hout[((size_t)b0 * 512 + t) * 256 + rank * 32 + jj] = h0new;
            hout[((size_t)b1 * 512 + t) * 256 + rank * 32 + jj] = h1new;
            if (n + 1 < 512) {
                int tn = dir ? (511 - (n + 1)) : (n + 1);
                const float* xp0 = xz + ((size_t)b0 * 512 + tn) * 1024 + rank * 32 + jj;
                const float* xp1 = xz + ((size_t)b1 * 512 + tn) * 1024 + rank * 32 + jj;
                x[0] = __ldg(xp0); x[1] = __ldg(xp0 + 256);
                x[2] = __ldg(xp0 + 512); x[3] = __ldg(xp0 + 768);
                x[4] = __ldg(xp1); x[5] = __ldg(xp1 + 256);
                x[6] = __ldg(xp1 + 512); x[7] = __ldg(xp1 + 768);
            }
        }
        asm volatile("barrier.cluster.wait.aligned;" ::: "memory");
    }
}

// ---------------------------------------------------------------------------
// K3: logits = [h_fwd ; h_bwd] @ W_d + b_d.  Warp per row, W_d^T in smem.
// ---------------------------------------------------------------------------
__global__ void k_logits(const float* __restrict__ Wd, const float* __restrict__ bd,
                         float* __restrict__ out)
{
    __shared__ float Wds[NTAGS_ * 512];
    __shared__ float bds[NTAGS_];
    int tid = threadIdx.x;
    for (int i = tid; i < 512 * NTAGS_; i += 256) {
        int k = i / NTAGS_, c = i - k * NTAGS_;
        Wds[c * 512 + k] = Wd[i];
    }
    if (tid < NTAGS_) bds[tid] = bd[tid];
    __syncthreads();

    int wid = tid >> 5, l = tid & 31;
    int r = blockIdx.x * 8 + wid;
    const float* pf = g_hf + (size_t)r * 256 + l;
    const float* pb = g_hb + (size_t)r * 256 + l;
    float hf[8], hbv[8];
#pragma unroll
    for (int i = 0; i < 8; i++) { hf[i] = pf[32 * i]; hbv[i] = pb[32 * i]; }

    float parts[NTAGS_];
#pragma unroll
    for (int c = 0; c < NTAGS_; c++) {
        float p = 0.f;
#pragma unroll
        for (int i = 0; i < 8; i++) {
            p = fmaf(hf[i],  Wds[c * 512 + 32 * i + l], p);
            p = fmaf(hbv[i], Wds[c * 512 + 256 + 32 * i + l], p);
        }
        parts[c] = p;
    }
#pragma unroll
    for (int c = 0; c < NTAGS_; c++)
#pragma unroll
        for (int off = 16; off; off >>= 1)
            parts[c] += __shfl_xor_sync(0xffffffffu, parts[c], off);

    if (l == 0) {
#pragma unroll
        for (int c = 0; c < NTAGS_; c++)
            out[(size_t)r * NTAGS_ + c] = parts[c] + bds[c];
    }
}

// ---------------------------------------------------------------------------
// K4: lens + CRF.  One warp per batch element; fast-math exp/log.
// ---------------------------------------------------------------------------
__global__ void k_crf(const int* __restrict__ text, const int* __restrict__ labels,
                      const float* __restrict__ trans, float* __restrict__ out)
{
    int b = blockIdx.x;
    int l = threadIdx.x;
    const float* lgb = out + (size_t)b * NS_ * NTAGS_;
    const int*   lab = labels + b * NS_;

    int cnt = 0;
#pragma unroll
    for (int i = 0; i < 16; i++) cnt += (text[b * NS_ + l + 32 * i] != 0) ? 1 : 0;
#pragma unroll
    for (int off = 16; off; off >>= 1) cnt += __shfl_xor_sync(0xffffffffu, cnt, off);
    int len = cnt;
    if (l == 0) out[LENS_OFF + b] = (float)len;

    float sc = 0.f;
#pragma unroll
    for (int i = 0; i < 16; i++) {
        int s = l + 32 * i;
        if (s < len)     sc += lgb[s * NTAGS_ + lab[s]];
        if (s < len - 1) sc += trans[lab[s] * NTAGS_ + lab[s + 1]];
    }
#pragma unroll
    for (int off = 16; off; off >>= 1) sc += __shfl_xor_sync(0xffffffffu, sc, off);

    int j = l;
    float tc[NTAGS_];
#pragma unroll
    for (int i = 0; i < NTAGS_; i++) tc[i] = trans[i * NTAGS_ + ((j < NTAGS_) ? j : 0)];
    float alpha = (j < NTAGS_) ? lgb[j] : -3.0e38f;

    float lt_next = (j < NTAGS_) ? lgb[NTAGS_ + j] : 0.f;
    for (int t = 1; t < NS_; t++) {
        float lt = lt_next;
        if (t + 1 < NS_) lt_next = (j < NTAGS_) ? lgb[(t + 1) * NTAGS_ + j] : 0.f;
        float vv[NTAGS_];
#pragma unroll
        for (int i = 0; i < NTAGS_; i++) {
            float ai = __shfl_sync(0xffffffffu, alpha, i);
            vv[i] = ai + tc[i];
        }
        float m01 = fmaxf(vv[0], vv[1]), m23 = fmaxf(vv[2], vv[3]);
        float m45 = fmaxf(vv[4], vv[5]), m67 = fmaxf(vv[6], vv[7]);
        float m03 = fmaxf(m01, m23), m47 = fmaxf(m45, m67);
        float mx = fmaxf(fmaxf(m03, m47), vv[8]);
        float e0 = __expf(vv[0] - mx) + __expf(vv[1] - mx);
        float e1 = __expf(vv[2] - mx) + __expf(vv[3] - mx);
        float e2 = __expf(vv[4] - mx) + __expf(vv[5] - mx);
        float e3 = __expf(vv[6] - mx) + __expf(vv[7] - mx);
        float sume = ((e0 + e1) + (e2 + e3)) + __expf(vv[8] - mx);
        float na = mx + __logf(sume) + lt;
        if ((t < len) && (j < NTAGS_)) alpha = na;
    }

    float a = (j < NTAGS_) ? alpha : -3.0e38f;
    float mx = a;
#pragma unroll
    for (int off = 16; off; off >>= 1) mx = fmaxf(mx, __shfl_xor_sync(0xffffffffu, mx, off));
    float e = (j < NTAGS_) ? __expf(a - mx) : 0.f;
#pragma unroll
    for (int off = 16; off; off >>= 1) e += __shfl_xor_sync(0xffffffffu, e, off);
    float lse = mx + __logf(e);

    if (l == 0) out[LL_OFF + b] = sc - lse;
}

// ---------------------------------------------------------------------------
extern "C" void kernel_launch(void* const* d_in, const int* in_sizes, int n_in,
                              void* d_out, int out_size)
{
    (void)in_sizes; (void)n_in; (void)out_size;
    const int*   text   = (const int*)d_in[0];
    const int*   labels = (const int*)d_in[1];
    const float* emb    = (const float*)d_in[2];
    const float* Wf     = (const float*)d_in[3];
    const float* Uf     = (const float*)d_in[4];
    const float* bf     = (const float*)d_in[5];
    const float* Wb     = (const float*)d_in[6];
    const float* Ub     = (const float*)d_in[7];
    const float* bb     = (const float*)d_in[8];
    const float* Wd     = (const float*)d_in[9];
    const float* bd     = (const float*)d_in[10];
    const float* trans  = (const float*)d_in[11];
    float* out = (float*)d_out;

    int smem1 = 64 * 130 * 8 + 128 * 64 * 4 + 64 * 4;          // 99584 B
    cudaFuncSetAttribute(k_ingemm, cudaFuncAttributeMaxDynamicSharedMemorySize, smem1);
    int smem2 = 4096 * 4 + 64 * 132 * 8;                        // 16384 + 67584 = 83968 B
    cudaFuncSetAttribute(k_lstm, cudaFuncAttributeMaxDynamicSharedMemorySize, smem2);

    k_ingemm<<<dim3(512, 32), 256, smem1>>>(text, emb, Wf, bf, Wb, bb);
    k_lstm<<<128, 512, smem2>>>(Uf, Ub);
    k_logits<<<4096, 256>>>(Wd, bd, out);
    k_crf<<<NB_, 32>>>(text, labels, trans, out);
}

// round 5
// speedup vs baseline: 1.0069x; 1.0069x over previous
#include <cuda_runtime.h>
#include <cstdint>
#include <math.h>

#define NB_ 64
#define NS_ 512
#define NHID_ 256
#define NTAGS_ 9
#define LOGITS_N (NB_ * NS_ * NTAGS_)   // 294912
#define LENS_OFF LOGITS_N               // 294912
#define LL_OFF   (LOGITS_N + NB_)       // 294976

// Scratch (device globals: no allocation allowed)
__device__ float g_xzf[NB_ * NS_ * 1024];   // x @ W_f + b_f
__device__ float g_xzb[NB_ * NS_ * 1024];   // x @ W_b + b_b
__device__ float g_hf[NB_ * NS_ * NHID_];
__device__ float g_hb[NB_ * NS_ * NHID_];

// ---------------- packed f32x2 helpers (sm_103a FFMA2 path) ----------------
__device__ __forceinline__ unsigned long long pk2(float lo, float hi) {
    unsigned long long r;
    asm("mov.b64 %0, {%1, %2};" : "=l"(r) : "f"(lo), "f"(hi));
    return r;
}
__device__ __forceinline__ float2 unpk2(unsigned long long v) {
    float2 r;
    asm("mov.b64 {%0, %1}, %2;" : "=f"(r.x), "=f"(r.y) : "l"(v));
    return r;
}
__device__ __forceinline__ unsigned long long fma2_(unsigned long long a,
                                                    unsigned long long b,
                                                    unsigned long long c) {
    unsigned long long d;
    asm("fma.rn.f32x2 %0, %1, %2, %3;" : "=l"(d) : "l"(a), "l"(b), "l"(c));
    return d;
}
__device__ __forceinline__ unsigned long long add2_(unsigned long long a,
                                                    unsigned long long b) {
    unsigned long long d;
    asm("add.rn.f32x2 %0, %1, %2;" : "=l"(d) : "l"(a), "l"(b));
    return d;
}

__device__ __forceinline__ float fsig(float x) {
    return __fdividef(1.0f, 1.0f + __expf(-x));
}
__device__ __forceinline__ float ftanh_(float x) {
    x = fminf(fmaxf(x, -15.0f), 15.0f);
    float e = __expf(2.0f * x);
    return __fdividef(e - 1.0f, e + 1.0f);
}

// ---------------------------------------------------------------------------
// K1: fused embedding-gather + input GEMM.
// A tile stored DUPLICATED in smem ((a,a) u64 pairs); B read as u64 col pairs.
// Grid: (512, 32): x = M tile (64 rows), y<16 -> fwd cols, y>=16 -> bwd cols.
// ---------------------------------------------------------------------------
__global__ void __launch_bounds__(256, 2)
k_ingemm(const int* __restrict__ text, const float* __restrict__ emb,
         const float* __restrict__ Wf, const float* __restrict__ bf,
         const float* __restrict__ Wb, const float* __restrict__ bb)
{
    extern __shared__ char sm1raw[];
    unsigned long long* As2 = (unsigned long long*)sm1raw;   // 64 x 130 u64 (dup, padded)
    float* Bs = (float*)(As2 + 64 * 130);                    // 128 x 64 f32
    int*   toks = (int*)(Bs + 128 * 64);                     // 64

    int bx = blockIdx.x, by = blockIdx.y, tid = threadIdx.x;
    const float* W; const float* bias; float* out; int ncol0;
    if (by < 16) { W = Wf; bias = bf; out = g_xzf; ncol0 = by * 64; }
    else         { W = Wb; bias = bb; out = g_xzb; ncol0 = (by - 16) * 64; }

    if (tid < 64) toks[tid] = text[bx * 64 + tid];
    __syncthreads();

    for (int i = tid; i < 2048; i += 256) {
        int m = i >> 5, k4 = i & 31;
        float4 v = __ldg((const float4*)(emb + (size_t)toks[m] * 128) + k4);
        ulonglong2 d0, d1;
        d0.x = pk2(v.x, v.x); d0.y = pk2(v.y, v.y);
        d1.x = pk2(v.z, v.z); d1.y = pk2(v.w, v.w);
        *(ulonglong2*)(As2 + m * 130 + k4 * 4)     = d0;
        *(ulonglong2*)(As2 + m * 130 + k4 * 4 + 2) = d1;
    }
    for (int i = tid; i < 2048; i += 256) {
        int k = i >> 4, n4 = i & 15;
        float4 v = __ldg((const float4*)(W + (size_t)k * 1024 + ncol0) + n4);
        *(float4*)(Bs + k * 64 + n4 * 4) = v;
    }
    __syncthreads();

    int tx = tid & 15, ty = tid >> 4;
    const unsigned long long* Bu = (const unsigned long long*)Bs;
    unsigned long long a01[4], a23[4];
#pragma unroll
    for (int i = 0; i < 4; i++) { a01[i] = 0ULL; a23[i] = 0ULL; }

#pragma unroll 2
    for (int kb = 0; kb < 128; kb += 4) {
        ulonglong2 ar0[4], ar1[4];
#pragma unroll
        for (int i = 0; i < 4; i++) {
            ar0[i] = *(const ulonglong2*)(As2 + (ty * 4 + i) * 130 + kb);
            ar1[i] = *(const ulonglong2*)(As2 + (ty * 4 + i) * 130 + kb + 2);
        }
#pragma unroll
        for (int kq = 0; kq < 4; kq++) {
            ulonglong2 b2 = *(const ulonglong2*)(Bu + (size_t)(kb + kq) * 32 + tx * 2);
#pragma unroll
            for (int i = 0; i < 4; i++) {
                unsigned long long ad = (kq == 0) ? ar0[i].x : (kq == 1) ? ar0[i].y
                                      : (kq == 2) ? ar1[i].x : ar1[i].y;
                a01[i] = fma2_(ad, b2.x, a01[i]);
                a23[i] = fma2_(ad, b2.y, a23[i]);
            }
        }
    }

    float4 bvv = *(const float4*)(bias + ncol0 + tx * 4);
#pragma unroll
    for (int i = 0; i < 4; i++) {
        float2 p01 = unpk2(a01[i]), p23 = unpk2(a23[i]);
        float4 o;
        o.x = p01.x + bvv.x; o.y = p01.y + bvv.y;
        o.z = p23.x + bvv.z; o.w = p23.y + bvv.w;
        *(float4*)(out + (size_t)(bx * 64 + ty * 4 + i) * 1024 + ncol0 + tx * 4) = o;
    }
}

// ---------------------------------------------------------------------------
// K2: LSTM recurrence. 16 clusters x 8 CTAs (dir, batch-group of 8 rows).
// CTA owns 32 units; Uc in SMEM, gate-interleaved cols (c = unit*4 + gate) so
// one LDS.128 fetches a unit's 4 gate weights. h state TRANSPOSED [k][batch]
// in smem: batch-pairs load directly as u64 -> only 4 pk2 per k (U dup).
// 16 warps split K (16 each); batch-paired u64 partials in smem; 128 consumer
// threads (bp,jj) reduce + gates + DSMEM v2 push. U stays in SMEM (R3's
// register-U spilled; that was the R4 regression).
// ---------------------------------------------------------------------------
__global__ void __cluster_dims__(8, 1, 1) __launch_bounds__(512, 1)
k_lstm(const float* __restrict__ Uf, const float* __restrict__ Ub)
{
    extern __shared__ float sm2[];
    float* Uc  = sm2;                                        // 256 x 128 = 128KB
    float* hbt = sm2 + 32768;                                // 2 x 256 x 8 = 16KB
    unsigned long long* zpu = (unsigned long long*)(hbt + 4096); // 16*512 u64 = 64KB

    int tid = threadIdx.x;
    unsigned rank;
    asm("mov.u32 %0, %%cluster_ctarank;" : "=r"(rank));
    int cl = blockIdx.x >> 3;
    int dir = cl & 1, bg = cl >> 1;
    const float* U    = dir ? Ub     : Uf;
    const float* xz   = dir ? g_xzb  : g_xzf;
    float*       hout = dir ? g_hb   : g_hf;

    int w = tid >> 5, l = tid & 31;
    int k0 = w * 16;

    // Uc[k*128 + unit*4 + g] = U[k*1024 + g*256 + rank*32 + unit]
    for (int idx = tid; idx < 32768; idx += 512) {
        int k = idx >> 7, c = idx & 127;
        int unit = c >> 2, g = c & 3;
        Uc[idx] = __ldg(U + (size_t)k * 1024 + g * 256 + rank * 32 + unit);
    }
    for (int i = tid; i < 4096; i += 512) hbt[i] = 0.0f;

    bool cons = (tid < 128);
    int bp = tid >> 5;          // consumer batch-pair 0..3
    int jj = l;                 // consumer unit 0..31
    int b0 = bg * 8 + 2 * bp, b1 = b0 + 1;
    float cst0 = 0.f, cst1 = 0.f;
    float h0new = 0.f, h1new = 0.f;
    uint32_t ra[8];
    float x[8];
    if (cons) {
        uint32_t hb_addr = (uint32_t)__cvta_generic_to_shared(hbt);
        uint32_t loff = hb_addr + (uint32_t)(((rank * 32 + jj) * 8 + 2 * bp) * 4);
#pragma unroll
        for (int dc = 0; dc < 8; dc++)
            asm volatile("mapa.shared::cluster.u32 %0, %1, %2;" : "=r"(ra[dc]) : "r"(loff), "r"(dc));
        int t0 = dir ? 511 : 0;
        const float* xp0 = xz + ((size_t)b0 * 512 + t0) * 1024 + rank * 32 + jj;
        const float* xp1 = xz + ((size_t)b1 * 512 + t0) * 1024 + rank * 32 + jj;
        x[0] = __ldg(xp0); x[1] = __ldg(xp0 + 256); x[2] = __ldg(xp0 + 512); x[3] = __ldg(xp0 + 768);
        x[4] = __ldg(xp1); x[5] = __ldg(xp1 + 256); x[6] = __ldg(xp1 + 512); x[7] = __ldg(xp1 + 768);
    }
    asm volatile("barrier.cluster.arrive.aligned;\n\tbarrier.cluster.wait.aligned;" ::: "memory");

    for (int n = 0; n < 512; n++) {
        int cur = n & 1, nxt = cur ^ 1;
        int t = dir ? (511 - n) : n;

        // GEMM: acc[pair][gate] (each u64 = batches (2p, 2p+1))
        const float* hc = hbt + cur * 2048;
        unsigned long long acc[4][4];
#pragma unroll
        for (int p = 0; p < 4; p++)
#pragma unroll
            for (int g = 0; g < 4; g++) acc[p][g] = 0ULL;

#pragma unroll
        for (int kk = 0; kk < 16; kk++) {
            int k = k0 + kk;
            float4 uq = *(const float4*)(Uc + k * 128 + l * 4);
            unsigned long long u0 = pk2(uq.x, uq.x);
            unsigned long long u1 = pk2(uq.y, uq.y);
            unsigned long long u2 = pk2(uq.z, uq.z);
            unsigned long long u3 = pk2(uq.w, uq.w);
            ulonglong2 hA = *(const ulonglong2*)(hc + k * 8);      // pairs 0,1
            ulonglong2 hB = *(const ulonglong2*)(hc + k * 8 + 4);  // pairs 2,3
            acc[0][0] = fma2_(hA.x, u0, acc[0][0]); acc[0][1] = fma2_(hA.x, u1, acc[0][1]);
            acc[0][2] = fma2_(hA.x, u2, acc[0][2]); acc[0][3] = fma2_(hA.x, u3, acc[0][3]);
            acc[1][0] = fma2_(hA.y, u0, acc[1][0]); acc[1][1] = fma2_(hA.y, u1, acc[1][1]);
            acc[1][2] = fma2_(hA.y, u2, acc[1][2]); acc[1][3] = fma2_(hA.y, u3, acc[1][3]);
            acc[2][0] = fma2_(hB.x, u0, acc[2][0]); acc[2][1] = fma2_(hB.x, u1, acc[2][1]);
            acc[2][2] = fma2_(hB.x, u2, acc[2][2]); acc[2][3] = fma2_(hB.x, u3, acc[2][3]);
            acc[3][0] = fma2_(hB.y, u0, acc[3][0]); acc[3][1] = fma2_(hB.y, u1, acc[3][1]);
            acc[3][2] = fma2_(hB.y, u2, acc[3][2]); acc[3][3] = fma2_(hB.y, u3, acc[3][3]);
        }
        // zpu slot(w,p,jj,g) = w*512 + p*128 + jj*4 + g
#pragma unroll
        for (int p = 0; p < 4; p++) {
            ulonglong2 v0, v1;
            v0.x = acc[p][0]; v0.y = acc[p][1];
            v1.x = acc[p][2]; v1.y = acc[p][3];
            *(ulonglong2*)(zpu + w * 512 + p * 128 + l * 4)     = v0;
            *(ulonglong2*)(zpu + w * 512 + p * 128 + l * 4 + 2) = v1;
        }
        __syncthreads();

        if (cons) {
            unsigned long long s0 = 0ULL, s1 = 0ULL, s2 = 0ULL, s3 = 0ULL;
#pragma unroll
            for (int w2 = 0; w2 < 16; w2++) {
                const unsigned long long* pz = zpu + w2 * 512 + bp * 128 + jj * 4;
                ulonglong2 a = *(const ulonglong2*)pz;
                ulonglong2 b = *(const ulonglong2*)(pz + 2);
                s0 = add2_(s0, a.x); s1 = add2_(s1, a.y);
                s2 = add2_(s2, b.x); s3 = add2_(s3, b.y);
            }
            float2 zi = unpk2(s0), zf = unpk2(s1), zg = unpk2(s2), zo = unpk2(s3);
            float i0 = fsig(zi.x + x[0]), f0 = fsig(zf.x + x[1]);
            float g0 = ftanh_(zg.x + x[2]), o0 = fsig(zo.x + x[3]);
            float i1 = fsig(zi.y + x[4]), f1 = fsig(zf.y + x[5]);
            float g1 = ftanh_(zg.y + x[6]), o1 = fsig(zo.y + x[7]);
            cst0 = f0 * cst0 + i0 * g0;
            cst1 = f1 * cst1 + i1 * g1;
            h0new = o0 * ftanh_(cst0);
            h1new = o1 * ftanh_(cst1);

            uint32_t poff = (uint32_t)(nxt * 2048 * 4);
#pragma unroll
            for (int dc = 0; dc < 8; dc++)
                asm volatile("st.shared::cluster.v2.f32 [%0], {%1, %2};"
                             :: "r"(ra[dc] + poff), "f"(h0new), "f"(h1new));
        }
        asm volatile("barrier.cluster.arrive.aligned;" ::: "memory");

        // barrier shadow: global h stores + next-step xz prefetch
        if (cons) {
            hout[((size_t)b0 * 512 + t) * 256 + rank * 32 + jj] = h0new;
            hout[((size_t)b1 * 512 + t) * 256 + rank * 32 + jj] = h1new;
            if (n + 1 < 512) {
                int tn = dir ? (511 - (n + 1)) : (n + 1);
                const float* xp0 = xz + ((size_t)b0 * 512 + tn) * 1024 + rank * 32 + jj;
                const float* xp1 = xz + ((size_t)b1 * 512 + tn) * 1024 + rank * 32 + jj;
                x[0] = __ldg(xp0); x[1] = __ldg(xp0 + 256);
                x[2] = __ldg(xp0 + 512); x[3] = __ldg(xp0 + 768);
                x[4] = __ldg(xp1); x[5] = __ldg(xp1 + 256);
                x[6] = __ldg(xp1 + 512); x[7] = __ldg(xp1 + 768);
            }
        }
        asm volatile("barrier.cluster.wait.aligned;" ::: "memory");
    }
}

// ---------------------------------------------------------------------------
// K3: logits = [h_fwd ; h_bwd] @ W_d + b_d.  Warp per row, W_d^T in smem.
// ---------------------------------------------------------------------------
__global__ void k_logits(const float* __restrict__ Wd, const float* __restrict__ bd,
                         float* __restrict__ out)
{
    __shared__ float Wds[NTAGS_ * 512];
    __shared__ float bds[NTAGS_];
    int tid = threadIdx.x;
    for (int i = tid; i < 512 * NTAGS_; i += 256) {
        int k = i / NTAGS_, c = i - k * NTAGS_;
        Wds[c * 512 + k] = Wd[i];
    }
    if (tid < NTAGS_) bds[tid] = bd[tid];
    __syncthreads();

    int wid = tid >> 5, l = tid & 31;
    int r = blockIdx.x * 8 + wid;
    const float* pf = g_hf + (size_t)r * 256 + l;
    const float* pb = g_hb + (size_t)r * 256 + l;
    float hf[8], hbv[8];
#pragma unroll
    for (int i = 0; i < 8; i++) { hf[i] = pf[32 * i]; hbv[i] = pb[32 * i]; }

    float parts[NTAGS_];
#pragma unroll
    for (int c = 0; c < NTAGS_; c++) {
        float p = 0.f;
#pragma unroll
        for (int i = 0; i < 8; i++) {
            p = fmaf(hf[i],  Wds[c * 512 + 32 * i + l], p);
            p = fmaf(hbv[i], Wds[c * 512 + 256 + 32 * i + l], p);
        }
        parts[c] = p;
    }
#pragma unroll
    for (int c = 0; c < NTAGS_; c++)
#pragma unroll
        for (int off = 16; off; off >>= 1)
            parts[c] += __shfl_xor_sync(0xffffffffu, parts[c], off);

    if (l == 0) {
#pragma unroll
        for (int c = 0; c < NTAGS_; c++)
            out[(size_t)r * NTAGS_ + c] = parts[c] + bds[c];
    }
}

// ---------------------------------------------------------------------------
// K4: lens + CRF.  One warp per batch element; fast-math exp/log.
// ---------------------------------------------------------------------------
__global__ void k_crf(const int* __restrict__ text, const int* __restrict__ labels,
                      const float* __restrict__ trans, float* __restrict__ out)
{
    int b = blockIdx.x;
    int l = threadIdx.x;
    const float* lgb = out + (size_t)b * NS_ * NTAGS_;
    const int*   lab = labels + b * NS_;

    int cnt = 0;
#pragma unroll
    for (int i = 0; i < 16; i++) cnt += (text[b * NS_ + l + 32 * i] != 0) ? 1 : 0;
#pragma unroll
    for (int off = 16; off; off >>= 1) cnt += __shfl_xor_sync(0xffffffffu, cnt, off);
    int len = cnt;
    if (l == 0) out[LENS_OFF + b] = (float)len;

    float sc = 0.f;
#pragma unroll
    for (int i = 0; i < 16; i++) {
        int s = l + 32 * i;
        if (s < len)     sc += lgb[s * NTAGS_ + lab[s]];
        if (s < len - 1) sc += trans[lab[s] * NTAGS_ + lab[s + 1]];
    }
#pragma unroll
    for (int off = 16; off; off >>= 1) sc += __shfl_xor_sync(0xffffffffu, sc, off);

    int j = l;
    float tc[NTAGS_];
#pragma unroll
    for (int i = 0; i < NTAGS_; i++) tc[i] = trans[i * NTAGS_ + ((j < NTAGS_) ? j : 0)];
    float alpha = (j < NTAGS_) ? lgb[j] : -3.0e38f;

    float lt_next = (j < NTAGS_) ? lgb[NTAGS_ + j] : 0.f;
    for (int t = 1; t < NS_; t++) {
        float lt = lt_next;
        if (t + 1 < NS_) lt_next = (j < NTAGS_) ? lgb[(t + 1) * NTAGS_ + j] : 0.f;
        float vv[NTAGS_];
#pragma unroll
        for (int i = 0; i < NTAGS_; i++) {
            float ai = __shfl_sync(0xffffffffu, alpha, i);
            vv[i] = ai + tc[i];
        }
        float m01 = fmaxf(vv[0], vv[1]), m23 = fmaxf(vv[2], vv[3]);
        float m45 = fmaxf(vv[4], vv[5]), m67 = fmaxf(vv[6], vv[7]);
        float m03 = fmaxf(m01, m23), m47 = fmaxf(m45, m67);
        float mx = fmaxf(fmaxf(m03, m47), vv[8]);
        float e0 = __expf(vv[0] - mx) + __expf(vv[1] - mx);
        float e1 = __expf(vv[2] - mx) + __expf(vv[3] - mx);
        float e2 = __expf(vv[4] - mx) + __expf(vv[5] - mx);
        float e3 = __expf(vv[6] - mx) + __expf(vv[7] - mx);
        float sume = ((e0 + e1) + (e2 + e3)) + __expf(vv[8] - mx);
        float na = mx + __logf(sume) + lt;
        if ((t < len) && (j < NTAGS_)) alpha = na;
    }

    float a = (j < NTAGS_) ? alpha : -3.0e38f;
    float mx = a;
#pragma unroll
    for (int off = 16; off; off >>= 1) mx = fmaxf(mx, __shfl_xor_sync(0xffffffffu, mx, off));
    float e = (j < NTAGS_) ? __expf(a - mx) : 0.f;
#pragma unroll
    for (int off = 16; off; off >>= 1) e += __shfl_xor_sync(0xffffffffu, e, off);
    float lse = mx + __logf(e);

    if (l == 0) out[LL_OFF + b] = sc - lse;
}

// ---------------------------------------------------------------------------
extern "C" void kernel_launch(void* const* d_in, const int* in_sizes, int n_in,
                              void* d_out, int out_size)
{
    (void)in_sizes; (void)n_in; (void)out_size;
    const int*   text   = (const int*)d_in[0];
    const int*   labels = (const int*)d_in[1];
    const float* emb    = (const float*)d_in[2];
    const float* Wf     = (const float*)d_in[3];
    const float* Uf     = (const float*)d_in[4];
    const float* bf     = (const float*)d_in[5];
    const float* Wb     = (const float*)d_in[6];
    const float* Ub     = (const float*)d_in[7];
    const float* bb     = (const float*)d_in[8];
    const float* Wd     = (const float*)d_in[9];
    const float* bd     = (const float*)d_in[10];
    const float* trans  = (const float*)d_in[11];
    float* out = (float*)d_out;

    int smem1 = 64 * 130 * 8 + 128 * 64 * 4 + 64 * 4;           // 99584 B
    cudaFuncSetAttribute(k_ingemm, cudaFuncAttributeMaxDynamicSharedMemorySize, smem1);
    int smem2 = 32768 * 4 + 4096 * 4 + 8192 * 8;                // 128K+16K+64K = 212992 B
    cudaFuncSetAttribute(k_lstm, cudaFuncAttributeMaxDynamicSharedMemorySize, smem2);

    k_ingemm<<<dim3(512, 32), 256, smem1>>>(text, emb, Wf, bf, Wb, bb);
    k_lstm<<<128, 512, smem2>>>(Uf, Ub);
    k_logits<<<4096, 256>>>(Wd, bd, out);
    k_crf<<<NB_, 32>>>(text, labels, trans, out);
}

// round 6
// speedup vs baseline: 1.2965x; 1.2875x over previous
#include <cuda_runtime.h>
#include <cstdint>
#include <math.h>

#define NB_ 64
#define NS_ 512
#define NHID_ 256
#define NTAGS_ 9
#define LOGITS_N (NB_ * NS_ * NTAGS_)   // 294912
#define LENS_OFF LOGITS_N               // 294912
#define LL_OFF   (LOGITS_N + NB_)       // 294976

// Scratch (device globals: no allocation allowed)
__device__ float g_xzf[NB_ * NS_ * 1024];   // x @ W_f + b_f
__device__ float g_xzb[NB_ * NS_ * 1024];   // x @ W_b + b_b
__device__ float g_hf[NB_ * NS_ * NHID_];
__device__ float g_hb[NB_ * NS_ * NHID_];

// ---------------- packed f32x2 helpers (sm_103a FFMA2 path) ----------------
__device__ __forceinline__ unsigned long long pk2(float lo, float hi) {
    unsigned long long r;
    asm("mov.b64 %0, {%1, %2};" : "=l"(r) : "f"(lo), "f"(hi));
    return r;
}
__device__ __forceinline__ float2 unpk2(unsigned long long v) {
    float2 r;
    asm("mov.b64 {%0, %1}, %2;" : "=f"(r.x), "=f"(r.y) : "l"(v));
    return r;
}
__device__ __forceinline__ unsigned long long fma2_(unsigned long long a,
                                                    unsigned long long b,
                                                    unsigned long long c) {
    unsigned long long d;
    asm("fma.rn.f32x2 %0, %1, %2, %3;" : "=l"(d) : "l"(a), "l"(b), "l"(c));
    return d;
}
__device__ __forceinline__ unsigned long long add2_(unsigned long long a,
                                                    unsigned long long b) {
    unsigned long long d;
    asm("add.rn.f32x2 %0, %1, %2;" : "=l"(d) : "l"(a), "l"(b));
    return d;
}

__device__ __forceinline__ float fsig(float x) {
    return __fdividef(1.0f, 1.0f + __expf(-x));
}
__device__ __forceinline__ float ftanh_(float x) {
    x = fminf(fmaxf(x, -15.0f), 15.0f);
    float e = __expf(2.0f * x);
    return __fdividef(e - 1.0f, e + 1.0f);
}

// ---------------------------------------------------------------------------
// K1: fused embedding-gather + input GEMM (A duplicated in smem, u64 B pairs).
// ---------------------------------------------------------------------------
__global__ void __launch_bounds__(256, 2)
k_ingemm(const int* __restrict__ text, const float* __restrict__ emb,
         const float* __restrict__ Wf, const float* __restrict__ bf,
         const float* __restrict__ Wb, const float* __restrict__ bb)
{
    extern __shared__ char sm1raw[];
    unsigned long long* As2 = (unsigned long long*)sm1raw;   // 64 x 130 u64
    float* Bs = (float*)(As2 + 64 * 130);                    // 128 x 64 f32
    int*   toks = (int*)(Bs + 128 * 64);                     // 64

    int bx = blockIdx.x, by = blockIdx.y, tid = threadIdx.x;
    const float* W; const float* bias; float* out; int ncol0;
    if (by < 16) { W = Wf; bias = bf; out = g_xzf; ncol0 = by * 64; }
    else         { W = Wb; bias = bb; out = g_xzb; ncol0 = (by - 16) * 64; }

    if (tid < 64) toks[tid] = text[bx * 64 + tid];
    __syncthreads();

    for (int i = tid; i < 2048; i += 256) {
        int m = i >> 5, k4 = i & 31;
        float4 v = __ldg((const float4*)(emb + (size_t)toks[m] * 128) + k4);
        ulonglong2 d0, d1;
        d0.x = pk2(v.x, v.x); d0.y = pk2(v.y, v.y);
        d1.x = pk2(v.z, v.z); d1.y = pk2(v.w, v.w);
        *(ulonglong2*)(As2 + m * 130 + k4 * 4)     = d0;
        *(ulonglong2*)(As2 + m * 130 + k4 * 4 + 2) = d1;
    }
    for (int i = tid; i < 2048; i += 256) {
        int k = i >> 4, n4 = i & 15;
        float4 v = __ldg((const float4*)(W + (size_t)k * 1024 + ncol0) + n4);
        *(float4*)(Bs + k * 64 + n4 * 4) = v;
    }
    __syncthreads();

    int tx = tid & 15, ty = tid >> 4;
    const unsigned long long* Bu = (const unsigned long long*)Bs;
    unsigned long long a01[4], a23[4];
#pragma unroll
    for (int i = 0; i < 4; i++) { a01[i] = 0ULL; a23[i] = 0ULL; }

#pragma unroll 2
    for (int kb = 0; kb < 128; kb += 4) {
        ulonglong2 ar0[4], ar1[4];
#pragma unroll
        for (int i = 0; i < 4; i++) {
            ar0[i] = *(const ulonglong2*)(As2 + (ty * 4 + i) * 130 + kb);
            ar1[i] = *(const ulonglong2*)(As2 + (ty * 4 + i) * 130 + kb + 2);
        }
#pragma unroll
        for (int kq = 0; kq < 4; kq++) {
            ulonglong2 b2 = *(const ulonglong2*)(Bu + (size_t)(kb + kq) * 32 + tx * 2);
#pragma unroll
            for (int i = 0; i < 4; i++) {
                unsigned long long ad = (kq == 0) ? ar0[i].x : (kq == 1) ? ar0[i].y
                                      : (kq == 2) ? ar1[i].x : ar1[i].y;
                a01[i] = fma2_(ad, b2.x, a01[i]);
                a23[i] = fma2_(ad, b2.y, a23[i]);
            }
        }
    }

    float4 bvv = *(const float4*)(bias + ncol0 + tx * 4);
#pragma unroll
    for (int i = 0; i < 4; i++) {
        float2 p01 = unpk2(a01[i]), p23 = unpk2(a23[i]);
        float4 o;
        o.x = p01.x + bvv.x; o.y = p01.y + bvv.y;
        o.z = p23.x + bvv.z; o.w = p23.y + bvv.w;
        *(float4*)(out + (size_t)(bx * 64 + ty * 4 + i) * 1024 + ncol0 + tx * 4) = o;
    }
}

// ---------------------------------------------------------------------------
// K2: LSTM recurrence. 16 clusters x 8 CTAs. Conflict-free everywhere:
//  - GEMM: U gate-quad LDS.128 (stride 16B), h BROADCAST ulonglong2 loads
//    from transposed hbt[k][b]; acc = batch-pairs in f32x2 lanes.
//  - zpu layout [w][p][half][lane] (ulonglong2): writer lane-stride 16B.
//  - consumer warps (warp=bp, lane=jj): zpu reads lane-stride 16B; hout
//    coalesced; single 8-way-conflicted ST.64 into stg transpose.
//  - pusher warps 4-7: stg[m] contiguous, DSMEM push contiguous 8B stride.
// ---------------------------------------------------------------------------
__global__ void __cluster_dims__(8, 1, 1) __launch_bounds__(512, 1)
k_lstm(const float* __restrict__ Uf, const float* __restrict__ Ub)
{
    extern __shared__ float sm2[];
    float* Uc  = sm2;                                        // 256 x 128 = 128KB
    float* hbt = sm2 + 32768;                                // 2 x 256 x 8 = 16KB
    ulonglong2* zpu2 = (ulonglong2*)(hbt + 4096);            // 4096 x 16B = 64KB
    unsigned long long* stg = (unsigned long long*)(zpu2 + 4096); // 128 u64 = 1KB

    int tid = threadIdx.x;
    unsigned rank;
    asm("mov.u32 %0, %%cluster_ctarank;" : "=r"(rank));
    int cl = blockIdx.x >> 3;
    int dir = cl & 1, bg = cl >> 1;
    const float* U    = dir ? Ub     : Uf;
    const float* xz   = dir ? g_xzb  : g_xzf;
    float*       hout = dir ? g_hb   : g_hf;

    int w = tid >> 5, l = tid & 31;
    int k0 = w * 16;

    // Uc[k*128 + unit*4 + g] = U[k*1024 + g*256 + rank*32 + unit]
    for (int idx = tid; idx < 32768; idx += 512) {
        int k = idx >> 7, c = idx & 127;
        int unit = c >> 2, g = c & 3;
        Uc[idx] = __ldg(U + (size_t)k * 1024 + g * 256 + rank * 32 + unit);
    }
    for (int i = tid; i < 4096; i += 512) hbt[i] = 0.0f;

    // Consumer role: warps 0-3 (bp = w, jj = l) -> batches (2bp, 2bp+1)
    bool cons = (w < 4);
    int bp = w, jj = l;
    int b0 = bg * 8 + 2 * bp, b1 = b0 + 1;
    float cst0 = 0.f, cst1 = 0.f, h0new = 0.f, h1new = 0.f;
    float x[8];
    if (cons) {
        int t0 = dir ? 511 : 0;
        const float* xp0 = xz + ((size_t)b0 * 512 + t0) * 1024 + rank * 32 + jj;
        const float* xp1 = xz + ((size_t)b1 * 512 + t0) * 1024 + rank * 32 + jj;
        x[0] = __ldg(xp0); x[1] = __ldg(xp0 + 256); x[2] = __ldg(xp0 + 512); x[3] = __ldg(xp0 + 768);
        x[4] = __ldg(xp1); x[5] = __ldg(xp1 + 256); x[6] = __ldg(xp1 + 512); x[7] = __ldg(xp1 + 768);
    }
    // Pusher role: warps 4-7 (m = tid-128; pjj = m>>2, pbp = m&3)
    bool push_w = (w >= 4 && w < 8);
    int m = tid - 128;
    uint32_t ra[8];
    if (push_w) {
        int pjj = m >> 2, pbp = m & 3;
        uint32_t hb_addr = (uint32_t)__cvta_generic_to_shared(hbt);
        uint32_t loff = hb_addr + (uint32_t)(((rank * 32 + pjj) * 8 + 2 * pbp) * 4);
#pragma unroll
        for (int dc = 0; dc < 8; dc++)
            asm volatile("mapa.shared::cluster.u32 %0, %1, %2;" : "=r"(ra[dc]) : "r"(loff), "r"(dc));
    }
    asm volatile("barrier.cluster.arrive.aligned;\n\tbarrier.cluster.wait.aligned;" ::: "memory");

    for (int n = 0; n < 512; n++) {
        int cur = n & 1, nxt = cur ^ 1;
        int t = dir ? (511 - n) : n;

        // GEMM: all 16 warps, K slice of 16
        const float* hc = hbt + cur * 2048;
        unsigned long long acc[4][4];
#pragma unroll
        for (int p = 0; p < 4; p++)
#pragma unroll
            for (int g = 0; g < 4; g++) acc[p][g] = 0ULL;

#pragma unroll
        for (int kk = 0; kk < 16; kk++) {
            int k = k0 + kk;
            float4 uq = *(const float4*)(Uc + k * 128 + l * 4);      // stride 16B, CF
            unsigned long long u0 = pk2(uq.x, uq.x);
            unsigned long long u1 = pk2(uq.y, uq.y);
            unsigned long long u2 = pk2(uq.z, uq.z);
            unsigned long long u3 = pk2(uq.w, uq.w);
            ulonglong2 hA = *(const ulonglong2*)(hc + k * 8);        // broadcast
            ulonglong2 hB = *(const ulonglong2*)(hc + k * 8 + 4);    // broadcast
            acc[0][0] = fma2_(hA.x, u0, acc[0][0]); acc[0][1] = fma2_(hA.x, u1, acc[0][1]);
            acc[0][2] = fma2_(hA.x, u2, acc[0][2]); acc[0][3] = fma2_(hA.x, u3, acc[0][3]);
            acc[1][0] = fma2_(hA.y, u0, acc[1][0]); acc[1][1] = fma2_(hA.y, u1, acc[1][1]);
            acc[1][2] = fma2_(hA.y, u2, acc[1][2]); acc[1][3] = fma2_(hA.y, u3, acc[1][3]);
            acc[2][0] = fma2_(hB.x, u0, acc[2][0]); acc[2][1] = fma2_(hB.x, u1, acc[2][1]);
            acc[2][2] = fma2_(hB.x, u2, acc[2][2]); acc[2][3] = fma2_(hB.x, u3, acc[2][3]);
            acc[3][0] = fma2_(hB.y, u0, acc[3][0]); acc[3][1] = fma2_(hB.y, u1, acc[3][1]);
            acc[3][2] = fma2_(hB.y, u2, acc[3][2]); acc[3][3] = fma2_(hB.y, u3, acc[3][3]);
        }
        // zpu[w][p][half][lane]: writer lane-stride 16B, conflict-free
#pragma unroll
        for (int p = 0; p < 4; p++) {
            ulonglong2 h0v, h1v;
            h0v.x = acc[p][0]; h0v.y = acc[p][1];
            h1v.x = acc[p][2]; h1v.y = acc[p][3];
            zpu2[((w * 4 + p) * 2 + 0) * 32 + l] = h0v;
            zpu2[((w * 4 + p) * 2 + 1) * 32 + l] = h1v;
        }
        __syncthreads();

        if (cons) {
            unsigned long long s0 = 0ULL, s1 = 0ULL, s2 = 0ULL, s3 = 0ULL;
#pragma unroll
            for (int w2 = 0; w2 < 16; w2++) {
                ulonglong2 a = zpu2[((w2 * 4 + bp) * 2 + 0) * 32 + jj];  // stride 16B, CF
                ulonglong2 b = zpu2[((w2 * 4 + bp) * 2 + 1) * 32 + jj];
                s0 = add2_(s0, a.x); s1 = add2_(s1, a.y);
                s2 = add2_(s2, b.x); s3 = add2_(s3, b.y);
            }
            float2 zi = unpk2(s0), zf = unpk2(s1), zg = unpk2(s2), zo = unpk2(s3);
            float i0 = fsig(zi.x + x[0]), f0 = fsig(zf.x + x[1]);
            float g0 = ftanh_(zg.x + x[2]), o0 = fsig(zo.x + x[3]);
            float i1 = fsig(zi.y + x[4]), f1 = fsig(zf.y + x[5]);
            float g1 = ftanh_(zg.y + x[6]), o1 = fsig(zo.y + x[7]);
            cst0 = f0 * cst0 + i0 * g0;
            cst1 = f1 * cst1 + i1 * g1;
            h0new = o0 * ftanh_(cst0);
            h1new = o1 * ftanh_(cst1);
            stg[jj * 4 + bp] = pk2(h0new, h1new);   // single transposing ST.64
        }
        __syncthreads();

        if (push_w) {
            unsigned long long hv = stg[m];          // contiguous, CF
            uint32_t poff = (uint32_t)(nxt * 2048 * 4);
#pragma unroll
            for (int dc = 0; dc < 8; dc++)
                asm volatile("st.shared::cluster.b64 [%0], %1;"
                             :: "r"(ra[dc] + poff), "l"(hv));
        }
        asm volatile("barrier.cluster.arrive.aligned;" ::: "memory");

        // barrier shadow: consumers store hout + prefetch next xz
        if (cons) {
            hout[((size_t)b0 * 512 + t) * 256 + rank * 32 + jj] = h0new;
            hout[((size_t)b1 * 512 + t) * 256 + rank * 32 + jj] = h1new;
            if (n + 1 < 512) {
                int tn = dir ? (511 - (n + 1)) : (n + 1);
                const float* xp0 = xz + ((size_t)b0 * 512 + tn) * 1024 + rank * 32 + jj;
                const float* xp1 = xz + ((size_t)b1 * 512 + tn) * 1024 + rank * 32 + jj;
                x[0] = __ldg(xp0); x[1] = __ldg(xp0 + 256);
                x[2] = __ldg(xp0 + 512); x[3] = __ldg(xp0 + 768);
                x[4] = __ldg(xp1); x[5] = __ldg(xp1 + 256);
                x[6] = __ldg(xp1 + 512); x[7] = __ldg(xp1 + 768);
            }
        }
        asm volatile("barrier.cluster.wait.aligned;" ::: "memory");
    }
}

// ---------------------------------------------------------------------------
// K3: logits = [h_fwd ; h_bwd] @ W_d + b_d.  Warp per row, W_d^T in smem.
// ---------------------------------------------------------------------------
__global__ void k_logits(const float* __restrict__ Wd, const float* __restrict__ bd,
                         float* __restrict__ out)
{
    __shared__ float Wds[NTAGS_ * 512];
    __shared__ float bds[NTAGS_];
    int tid = threadIdx.x;
    for (int i = tid; i < 512 * NTAGS_; i += 256) {
        int k = i / NTAGS_, c = i - k * NTAGS_;
        Wds[c * 512 + k] = Wd[i];
    }
    if (tid < NTAGS_) bds[tid] = bd[tid];
    __syncthreads();

    int wid = tid >> 5, l = tid & 31;
    int r = blockIdx.x * 8 + wid;
    const float* pf = g_hf + (size_t)r * 256 + l;
    const float* pb = g_hb + (size_t)r * 256 + l;
    float hf[8], hbv[8];
#pragma unroll
    for (int i = 0; i < 8; i++) { hf[i] = pf[32 * i]; hbv[i] = pb[32 * i]; }

    float parts[NTAGS_];
#pragma unroll
    for (int c = 0; c < NTAGS_; c++) {
        float p = 0.f;
#pragma unroll
        for (int i = 0; i < 8; i++) {
            p = fmaf(hf[i],  Wds[c * 512 + 32 * i + l], p);
            p = fmaf(hbv[i], Wds[c * 512 + 256 + 32 * i + l], p);
        }
        parts[c] = p;
    }
#pragma unroll
    for (int c = 0; c < NTAGS_; c++)
#pragma unroll
        for (int off = 16; off; off >>= 1)
            parts[c] += __shfl_xor_sync(0xffffffffu, parts[c], off);

    if (l == 0) {
#pragma unroll
        for (int c = 0; c < NTAGS_; c++)
            out[(size_t)r * NTAGS_ + c] = parts[c] + bds[c];
    }
}

// ---------------------------------------------------------------------------
// K4: lens + CRF.  One warp per batch element; fast-math exp/log.
// ---------------------------------------------------------------------------
__global__ void k_crf(const int* __restrict__ text, const int* __restrict__ labels,
                      const float* __restrict__ trans, float* __restrict__ out)
{
    int b = blockIdx.x;
    int l = threadIdx.x;
    const float* lgb = out + (size_t)b * NS_ * NTAGS_;
    const int*   lab = labels + b * NS_;

    int cnt = 0;
#pragma unroll
    for (int i = 0; i < 16; i++) cnt += (text[b * NS_ + l + 32 * i] != 0) ? 1 : 0;
#pragma unroll
    for (int off = 16; off; off >>= 1) cnt += __shfl_xor_sync(0xffffffffu, cnt, off);
    int len = cnt;
    if (l == 0) out[LENS_OFF + b] = (float)len;

    float sc = 0.f;
#pragma unroll
    for (int i = 0; i < 16; i++) {
        int s = l + 32 * i;
        if (s < len)     sc += lgb[s * NTAGS_ + lab[s]];
        if (s < len - 1) sc += trans[lab[s] * NTAGS_ + lab[s + 1]];
    }
#pragma unroll
    for (int off = 16; off; off >>= 1) sc += __shfl_xor_sync(0xffffffffu, sc, off);

    int j = l;
    float tc[NTAGS_];
#pragma unroll
    for (int i = 0; i < NTAGS_; i++) tc[i] = trans[i * NTAGS_ + ((j < NTAGS_) ? j : 0)];
    float alpha = (j < NTAGS_) ? lgb[j] : -3.0e38f;

    float lt_next = (j < NTAGS_) ? lgb[NTAGS_ + j] : 0.f;
    for (int t = 1; t < NS_; t++) {
        float lt = lt_next;
        if (t + 1 < NS_) lt_next = (j < NTAGS_) ? lgb[(t + 1) * NTAGS_ + j] : 0.f;
        float vv[NTAGS_];
#pragma unroll
        for (int i = 0; i < NTAGS_; i++) {
            float ai = __shfl_sync(0xffffffffu, alpha, i);
            vv[i] = ai + tc[i];
        }
        float m01 = fmaxf(vv[0], vv[1]), m23 = fmaxf(vv[2], vv[3]);
        float m45 = fmaxf(vv[4], vv[5]), m67 = fmaxf(vv[6], vv[7]);
        float m03 = fmaxf(m01, m23), m47 = fmaxf(m45, m67);
        float mx = fmaxf(fmaxf(m03, m47), vv[8]);
        float e0 = __expf(vv[0] - mx) + __expf(vv[1] - mx);
        float e1 = __expf(vv[2] - mx) + __expf(vv[3] - mx);
        float e2 = __expf(vv[4] - mx) + __expf(vv[5] - mx);
        float e3 = __expf(vv[6] - mx) + __expf(vv[7] - mx);
        float sume = ((e0 + e1) + (e2 + e3)) + __expf(vv[8] - mx);
        float na = mx + __logf(sume) + lt;
        if ((t < len) && (j < NTAGS_)) alpha = na;
    }

    float a = (j < NTAGS_) ? alpha : -3.0e38f;
    float mx = a;
#pragma unroll
    for (int off = 16; off; off >>= 1) mx = fmaxf(mx, __shfl_xor_sync(0xffffffffu, mx, off));
    float e = (j < NTAGS_) ? __expf(a - mx) : 0.f;
#pragma unroll
    for (int off = 16; off; off >>= 1) e += __shfl_xor_sync(0xffffffffu, e, off);
    float lse = mx + __logf(e);

    if (l == 0) out[LL_OFF + b] = sc - lse;
}

// ---------------------------------------------------------------------------
extern "C" void kernel_launch(void* const* d_in, const int* in_sizes, int n_in,
                              void* d_out, int out_size)
{
    (void)in_sizes; (void)n_in; (void)out_size;
    const int*   text   = (const int*)d_in[0];
    const int*   labels = (const int*)d_in[1];
    const float* emb    = (const float*)d_in[2];
    const float* Wf     = (const float*)d_in[3];
    const float* Uf     = (const float*)d_in[4];
    const float* bf     = (const float*)d_in[5];
    const float* Wb     = (const float*)d_in[6];
    const float* Ub     = (const float*)d_in[7];
    const float* bb     = (const float*)d_in[8];
    const float* Wd     = (const float*)d_in[9];
    const float* bd     = (const float*)d_in[10];
    const float* trans  = (const float*)d_in[11];
    float* out = (float*)d_out;

    int smem1 = 64 * 130 * 8 + 128 * 64 * 4 + 64 * 4;           // 99584 B
    cudaFuncSetAttribute(k_ingemm, cudaFuncAttributeMaxDynamicSharedMemorySize, smem1);
    int smem2 = 32768 * 4 + 4096 * 4 + 4096 * 16 + 128 * 8;     // 128K+16K+64K+1K
    cudaFuncSetAttribute(k_lstm, cudaFuncAttributeMaxDynamicSharedMemorySize, smem2);

    k_ingemm<<<dim3(512, 32), 256, smem1>>>(text, emb, Wf, bf, Wb, bb);
    k_lstm<<<128, 512, smem2>>>(Uf, Ub);
    k_logits<<<4096, 256>>>(Wd, bd, out);
    k_crf<<<NB_, 32>>>(text, labels, trans, out);
}